// round 11
// baseline (speedup 1.0000x reference)
#include <cuda_runtime.h>
#include <cuda_bf16.h>
#include <cstdint>

#define EMB 300
#define HID 600
#define KP1 320   // padded K for gemm1 (multiple of 64)
#define KP2 640   // padded K for gemm2
#define NLAYERS 5
#define NMAX 50176
#define EMAX 1000000
#define BN_EPS 1e-5f

// ---------------- scratch (static __device__ globals; no allocations) -------
__device__ __align__(128) float g_hbuf0[NMAX * EMB];
__device__ __align__(128) float g_hbuf1[NMAX * EMB];
__device__ __align__(128) unsigned short g_ahi[NMAX * KP1];
__device__ __align__(128) unsigned short g_alo[NMAX * KP1];
__device__ __align__(128) unsigned short g_h2hi[(size_t)NMAX * KP2];
__device__ __align__(128) unsigned short g_h2lo[(size_t)NMAX * KP2];
__device__ __align__(128) unsigned short g_wt1hi[NLAYERS * HID * KP1];
__device__ __align__(128) unsigned short g_wt1lo[NLAYERS * HID * KP1];
__device__ __align__(128) unsigned short g_wt2hi[NLAYERS * EMB * KP2];
__device__ __align__(128) unsigned short g_wt2lo[NLAYERS * EMB * KP2];
__device__ int g_deg[NMAX];
__device__ int g_rowptr[NMAX + 1];
__device__ int g_wofs[NMAX];
__device__ int g_csr[EMAX];
__device__ float g_sum[EMB], g_sumsq[EMB];
__device__ __align__(16) float g_scale[EMB];
__device__ __align__(16) float g_shift[EMB];
__device__ float g_cnt[4096];

// ---------------- PTX helpers -------------------------------------------------
__device__ __forceinline__ uint32_t smem_u32(const void* p) {
    uint32_t a;
    asm("{ .reg .u64 t; cvta.to.shared.u64 t, %1; cvt.u32.u64 %0, t; }" : "=r"(a) : "l"(p));
    return a;
}
__device__ __forceinline__ void cp16(uint32_t dsm, const void* gsrc, int sz) {
    asm volatile("cp.async.cg.shared.global [%0], [%1], 16, %2;"
                 :: "r"(dsm), "l"(gsrc), "r"(sz) : "memory");
}
#define CP_COMMIT() asm volatile("cp.async.commit_group;" ::: "memory")
#define CP_WAIT(n) asm volatile("cp.async.wait_group %0;" :: "n"(n) : "memory")

#define LDSM4(r, addr) \
    asm volatile("ldmatrix.sync.aligned.m8n8.x4.shared.b16 {%0,%1,%2,%3}, [%4];" \
                 : "=r"((r)[0]), "=r"((r)[1]), "=r"((r)[2]), "=r"((r)[3]) : "r"(addr))

#define MMA_BF16(d, a, b0, b1) \
    asm volatile("mma.sync.aligned.m16n8k16.row.col.f32.bf16.bf16.f32 " \
                 "{%0,%1,%2,%3}, {%4,%5,%6,%7}, {%8,%9}, {%0,%1,%2,%3};" \
                 : "+f"((d)[0]), "+f"((d)[1]), "+f"((d)[2]), "+f"((d)[3]) \
                 : "r"((a)[0]), "r"((a)[1]), "r"((a)[2]), "r"((a)[3]), "r"(b0), "r"(b1))

// ---------------- CSR build (once per launch) ---------------------------------
__global__ void zero_deg(int N) {
    int i = blockIdx.x * blockDim.x + threadIdx.x;
    if (i < N) g_deg[i] = 0;
}
__global__ void hist_dst(const int* __restrict__ dst, int E) {
    int e = blockIdx.x * blockDim.x + threadIdx.x;
    if (e < E) atomicAdd(&g_deg[__ldg(&dst[e])], 1);
}
__global__ void scan_deg(int N) {
    __shared__ int sm[1024];
    __shared__ int carry;
    int t = threadIdx.x;
    if (t == 0) carry = 0;
    __syncthreads();
    for (int base = 0; base < N; base += 1024) {
        int i = base + t;
        int v = (i < N) ? g_deg[i] : 0;
        sm[t] = v;
        __syncthreads();
#pragma unroll
        for (int off = 1; off < 1024; off <<= 1) {
            int x = (t >= off) ? sm[t - off] : 0;
            __syncthreads();
            sm[t] += x;
            __syncthreads();
        }
        if (i < N) {
            int ex = carry + sm[t] - v;
            g_rowptr[i] = ex;
            g_wofs[i] = ex;
        }
        __syncthreads();
        if (t == 1023) carry += sm[1023];
        __syncthreads();
    }
    if (t == 0) g_rowptr[N] = carry;
}
__global__ void fill_csr(const int* __restrict__ src, const int* __restrict__ dst, int E) {
    int e = blockIdx.x * blockDim.x + threadIdx.x;
    if (e >= E) return;
    int d = __ldg(&dst[e]);
    int p = atomicAdd(&g_wofs[d], 1);
    g_csr[p] = __ldg(&src[e]);
}

// ---------------- fused (BN+relu of prev layer) + gather + (1+eps) + split ----
// apply_bn=0 (layer 0): h is raw input.
// apply_bn=1: x = relu(h*scale + shift) applied on the fly to every read.
__global__ void gather_split(const float4* __restrict__ h, const float* __restrict__ eps,
                             int l, uint2* __restrict__ oh, uint2* __restrict__ ol,
                             long long n80, int apply_bn) {
    long long i = blockIdx.x * 256LL + threadIdx.x;
    if (i >= n80) return;
    int n = (int)(i / 80);
    int c = (int)(i % 80);
    if (c >= 75) {
        if (!apply_bn) {  // pads written once (layer 0); stay zero afterwards
            uint2 z = make_uint2(0u, 0u);
            oh[i] = z;
            ol[i] = z;
        }
        return;
    }
    float4 sc, sh;
    if (apply_bn) {
        sc = reinterpret_cast<const float4*>(g_scale)[c];
        sh = reinterpret_cast<const float4*>(g_shift)[c];
    }
    float e = 1.0f + __ldg(&eps[l]);
    float4 v = h[(size_t)n * 75 + c];
    if (apply_bn) {
        v.x = fmaxf(fmaf(v.x, sc.x, sh.x), 0.f);
        v.y = fmaxf(fmaf(v.y, sc.y, sh.y), 0.f);
        v.z = fmaxf(fmaf(v.z, sc.z, sh.z), 0.f);
        v.w = fmaxf(fmaf(v.w, sc.w, sh.w), 0.f);
    }
    v.x *= e; v.y *= e; v.z *= e; v.w *= e;
    int p0 = __ldg(&g_rowptr[n]);
    int p1 = __ldg(&g_rowptr[n + 1]);
    for (int p = p0; p < p1; p++) {
        int s = __ldg(&g_csr[p]);
        float4 u = __ldg(&h[(size_t)s * 75 + c]);
        if (apply_bn) {
            u.x = fmaxf(fmaf(u.x, sc.x, sh.x), 0.f);
            u.y = fmaxf(fmaf(u.y, sc.y, sh.y), 0.f);
            u.z = fmaxf(fmaf(u.z, sc.z, sh.z), 0.f);
            u.w = fmaxf(fmaf(u.w, sc.w, sh.w), 0.f);
        }
        v.x += u.x; v.y += u.y; v.z += u.z; v.w += u.w;
    }
    __nv_bfloat16 h0 = __float2bfloat16(v.x), h1 = __float2bfloat16(v.y);
    __nv_bfloat16 h2 = __float2bfloat16(v.z), h3 = __float2bfloat16(v.w);
    __nv_bfloat16 l0 = __float2bfloat16(v.x - __bfloat162float(h0));
    __nv_bfloat16 l1 = __float2bfloat16(v.y - __bfloat162float(h1));
    __nv_bfloat16 l2 = __float2bfloat16(v.z - __bfloat162float(h2));
    __nv_bfloat16 l3 = __float2bfloat16(v.w - __bfloat162float(h3));
    __nv_bfloat162 ph0 = __halves2bfloat162(h0, h1), ph1 = __halves2bfloat162(h2, h3);
    __nv_bfloat162 pl0 = __halves2bfloat162(l0, l1), pl1 = __halves2bfloat162(l2, l3);
    oh[i] = make_uint2(*reinterpret_cast<uint32_t*>(&ph0), *reinterpret_cast<uint32_t*>(&ph1));
    ol[i] = make_uint2(*reinterpret_cast<uint32_t*>(&pl0), *reinterpret_cast<uint32_t*>(&pl1));
}

// ---------------- prep: split weights into transposed bf16 hi/lo -------------
__global__ void prep_wt(const float* __restrict__ W, unsigned short* __restrict__ wh,
                        unsigned short* __restrict__ wl, int K, int Nd, int kpad, long long total) {
    long long i = blockIdx.x * 256LL + threadIdx.x;
    if (i >= total) return;
    int k = (int)(i % kpad);
    long long r = i / kpad;
    int n = (int)(r % Nd);
    int l = (int)(r / Nd);
    float v = 0.f;
    if (k < K) v = W[((size_t)l * K + k) * Nd + n];
    __nv_bfloat16 hi = __float2bfloat16(v);
    __nv_bfloat16 lo = __float2bfloat16(v - __bfloat162float(hi));
    wh[i] = *reinterpret_cast<unsigned short*>(&hi);
    wl[i] = *reinterpret_cast<unsigned short*>(&lo);
}

__global__ void zero_stats() {
    int t = threadIdx.x;
    if (t < EMB) { g_sum[t] = 0.f; g_sumsq[t] = 0.f; }
}
__global__ void zero_out_cnt(float* __restrict__ out, int G) {
    int i = blockIdx.x * blockDim.x + threadIdx.x;
    if (i < G * EMB) out[i] = 0.f;
    if (i < G) g_cnt[i] = 0.f;
}

// ---------------- HMMA bf16 GEMM (3-term split, 3-stage cp.async pipeline) -----
// OUT_BF16=1: o = relu(d+bias) -> Chi/Clo bf16, pads zeroed.
// OUT_BF16=0: o = d+bias -> Cf fp32, AND per-column sum/sumsq atomics (BN stats).
template <int OUT_BF16>
__global__ __launch_bounds__(256, 1) void gemm_mma(
    const unsigned short* __restrict__ Ahi, const unsigned short* __restrict__ Alo,
    const unsigned short* __restrict__ Bhi, const unsigned short* __restrict__ Blo,
    const float* __restrict__ bias, float* __restrict__ Cf,
    unsigned short* __restrict__ Chi, unsigned short* __restrict__ Clo,
    int M, int Nd, int kpad, int cpad) {
    extern __shared__ char smem[];
    const uint32_t sb = smem_u32(smem);
    const int tid = threadIdx.x;
    const int wid = tid >> 5;
    const int lid = tid & 31;
    const int wm = wid & 1;
    const int wn = wid >> 1;
    const int m0 = blockIdx.y * 128;
    const int n0 = blockIdx.x * 128;
    const int g = lid >> 2;
    const int tig = lid & 3;

    const unsigned short* mats[4] = {Ahi, Alo, Bhi, Blo};
    const int r0m[4] = {m0, m0, n0, n0};
    const int rmax[4] = {M, M, Nd, Nd};

    const int NC = kpad >> 6;
    const int lrow = tid >> 1;
    const int lcb = (tid & 1) * 4;

    auto issue_load = [&](int c) {
        const int k0 = c << 6;
        const uint32_t bbase = sb + (c % 3) * 65536;
#pragma unroll
        for (int mat = 0; mat < 4; mat++) {
            const int gr = r0m[mat] + lrow;
            const int ok = (gr < rmax[mat]) ? 16 : 0;
            const unsigned short* gptr =
                mats[mat] + (size_t)(ok ? gr : 0) * kpad + k0 + lcb * 8;
            const uint32_t mbase = bbase + mat * 16384 + lrow * 128;
            const int rsw = lrow & 7;
#pragma unroll
            for (int i = 0; i < 4; i++) {
                int chunk = lcb + i;
                cp16(mbase + (((chunk ^ rsw)) << 4), gptr + i * 8, ok);
            }
        }
        CP_COMMIT();
    };

    float acc[4][4][4];
#pragma unroll
    for (int a = 0; a < 4; a++)
#pragma unroll
        for (int b = 0; b < 4; b++)
#pragma unroll
            for (int c = 0; c < 4; c++) acc[a][b][c] = 0.f;

    const int arow = (lid & 15);
    const int achk = (lid >> 4);
    const int brow = (lid & 7) + ((lid & 16) ? 8 : 0);
    const int bchk = (lid >> 3) & 1;

    issue_load(0);
    if (NC > 1) issue_load(1);

    for (int c = 0; c < NC; c++) {
        if (c + 1 < NC) { CP_WAIT(1); } else { CP_WAIT(0); }
        __syncthreads();
        if (c + 2 < NC) issue_load(c + 2);

        const uint32_t bbase = sb + (c % 3) * 65536;
        const uint32_t sAh = bbase, sAl = bbase + 16384;
        const uint32_t sBh = bbase + 32768, sBl = bbase + 49152;

#pragma unroll
        for (int ks = 0; ks < 4; ks++) {
            const int kb8 = ks * 2;
            uint32_t aH[4][4], aL[4][4], bH[2][4], bL[2][4];
#pragma unroll
            for (int mi = 0; mi < 4; mi++) {
                int row = wm * 64 + mi * 16 + arow;
                int chunk = kb8 + achk;
                uint32_t off = row * 128 + ((chunk ^ (row & 7)) << 4);
                LDSM4(aH[mi], sAh + off);
                LDSM4(aL[mi], sAl + off);
            }
#pragma unroll
            for (int nj = 0; nj < 2; nj++) {
                int row = wn * 32 + nj * 16 + brow;
                int chunk = kb8 + bchk;
                uint32_t off = row * 128 + ((chunk ^ (row & 7)) << 4);
                LDSM4(bH[nj], sBh + off);
                LDSM4(bL[nj], sBl + off);
            }
#pragma unroll
            for (int mi = 0; mi < 4; mi++)
#pragma unroll
                for (int nj = 0; nj < 2; nj++)
#pragma unroll
                    for (int h = 0; h < 2; h++) {
                        float* d = acc[mi][nj * 2 + h];
                        MMA_BF16(d, aH[mi], bH[nj][h * 2], bH[nj][h * 2 + 1]);
                        MMA_BF16(d, aL[mi], bH[nj][h * 2], bH[nj][h * 2 + 1]);
                        MMA_BF16(d, aH[mi], bL[nj][h * 2], bL[nj][h * 2 + 1]);
                    }
        }
    }

    // epilogue (+ BN stats accumulation when OUT_BF16==0)
    float sacc[4][2], s2acc[4][2];
#pragma unroll
    for (int nj = 0; nj < 4; nj++) { sacc[nj][0] = sacc[nj][1] = 0.f; s2acc[nj][0] = s2acc[nj][1] = 0.f; }

#pragma unroll
    for (int mi = 0; mi < 4; mi++) {
#pragma unroll
        for (int nj = 0; nj < 4; nj++) {
            const float* d = acc[mi][nj];
            int c = n0 + wn * 32 + nj * 8 + 2 * tig;
            float bs0 = 0.f, bs1 = 0.f;
            if (c < Nd) bs0 = __ldg(&bias[c]);
            if (c + 1 < Nd) bs1 = __ldg(&bias[c + 1]);
#pragma unroll
            for (int half = 0; half < 2; half++) {
                int r = m0 + wm * 64 + mi * 16 + g + half * 8;
                if (r >= M) continue;
                float o0 = (c < Nd) ? d[half * 2] + bs0 : 0.f;
                float o1 = (c + 1 < Nd) ? d[half * 2 + 1] + bs1 : 0.f;
                if (OUT_BF16) {
                    o0 = fmaxf(o0, 0.f);
                    o1 = fmaxf(o1, 0.f);
                    __nv_bfloat16 h0 = __float2bfloat16(o0), h1 = __float2bfloat16(o1);
                    __nv_bfloat16 l0 = __float2bfloat16(o0 - __bfloat162float(h0));
                    __nv_bfloat16 l1 = __float2bfloat16(o1 - __bfloat162float(h1));
                    __nv_bfloat162 ph = __halves2bfloat162(h0, h1);
                    __nv_bfloat162 pl = __halves2bfloat162(l0, l1);
                    *reinterpret_cast<uint32_t*>(Chi + (size_t)r * cpad + c) =
                        *reinterpret_cast<uint32_t*>(&ph);
                    *reinterpret_cast<uint32_t*>(Clo + (size_t)r * cpad + c) =
                        *reinterpret_cast<uint32_t*>(&pl);
                } else {
                    if (c < Nd) {
                        float2 v = make_float2(o0, o1);
                        *reinterpret_cast<float2*>(Cf + (size_t)r * cpad + c) = v;
                    }
                    sacc[nj][0] += o0;
                    s2acc[nj][0] += o0 * o0;
                    sacc[nj][1] += o1;
                    s2acc[nj][1] += o1 * o1;
                }
            }
        }
    }

    if (!OUT_BF16) {
        __syncthreads();
        float* st = reinterpret_cast<float*>(smem);
        if (tid < 256) st[tid] = 0.f;
        __syncthreads();
#pragma unroll
        for (int nj = 0; nj < 4; nj++) {
#pragma unroll
            for (int cp = 0; cp < 2; cp++) {
                float s = sacc[nj][cp], s2 = s2acc[nj][cp];
                s += __shfl_xor_sync(0xFFFFFFFFu, s, 4);
                s2 += __shfl_xor_sync(0xFFFFFFFFu, s2, 4);
                s += __shfl_xor_sync(0xFFFFFFFFu, s, 8);
                s2 += __shfl_xor_sync(0xFFFFFFFFu, s2, 8);
                s += __shfl_xor_sync(0xFFFFFFFFu, s, 16);
                s2 += __shfl_xor_sync(0xFFFFFFFFu, s2, 16);
                if (g == 0) {
                    int cl = wn * 32 + nj * 8 + 2 * tig + cp;
                    atomicAdd(&st[cl], s);
                    atomicAdd(&st[128 + cl], s2);
                }
            }
        }
        __syncthreads();
        if (tid < 128) {
            int c = n0 + tid;
            if (c < Nd) {
                atomicAdd(&g_sum[c], st[tid]);
                atomicAdd(&g_sumsq[c], st[128 + tid]);
            }
        }
    }
}

// ---------------- BN finalize: scale/shift per channel -------------------------
__global__ void bn_finalize(const float* __restrict__ gamma, const float* __restrict__ beta,
                            int N) {
    int c = threadIdx.x;
    if (c >= EMB) return;
    float invN = 1.0f / (float)N;
    float mu = g_sum[c] * invN;
    float var = g_sumsq[c] * invN - mu * mu;
    float istd = rsqrtf(var + BN_EPS);
    float sc = istd * __ldg(&gamma[c]);
    g_scale[c] = sc;
    g_shift[c] = __ldg(&beta[c]) - mu * sc;
}

// ---------------- readout (applies last layer's BN, no relu) -------------------
__global__ void readout_cnt(const int* __restrict__ gids, int N) {
    int n = blockIdx.x * blockDim.x + threadIdx.x;
    if (n < N) atomicAdd(&g_cnt[__ldg(&gids[n])], 1.0f);
}
__global__ void readout_accum(const float* __restrict__ h, const int* __restrict__ gids,
                              float* __restrict__ out, long long total) {
    long long idx = blockIdx.x * 256LL + threadIdx.x;
    if (idx >= total) return;
    int n = (int)(idx / 75);
    int c = (int)(idx % 75);
    int g = __ldg(&gids[n]);
    float4 sc = reinterpret_cast<const float4*>(g_scale)[c];
    float4 sh = reinterpret_cast<const float4*>(g_shift)[c];
    float4 v = reinterpret_cast<const float4*>(h + (size_t)n * EMB)[c];
    v.x = fmaf(v.x, sc.x, sh.x);
    v.y = fmaf(v.y, sc.y, sh.y);
    v.z = fmaf(v.z, sc.z, sh.z);
    v.w = fmaf(v.w, sc.w, sh.w);
    atomicAdd(reinterpret_cast<float4*>(out + (size_t)g * EMB) + c, v);
}
__global__ void readout_div(float* __restrict__ out, int G) {
    int i = blockIdx.x * blockDim.x + threadIdx.x;
    if (i < G * EMB) out[i] /= fmaxf(g_cnt[i / EMB], 1.0f);
}

// ---------------- launch ------------------------------------------------------
extern "C" void kernel_launch(void* const* d_in, const int* in_sizes, int n_in,
                              void* d_out, int out_size) {
    (void)n_in;
    const float* node_feats = (const float*)d_in[0];
    const float* W1 = (const float*)d_in[1];
    const float* b1v = (const float*)d_in[2];
    const float* W2 = (const float*)d_in[3];
    const float* b2v = (const float*)d_in[4];
    const float* eps = (const float*)d_in[5];
    const float* gamma = (const float*)d_in[6];
    const float* beta = (const float*)d_in[7];
    const int* src = (const int*)d_in[8];
    const int* dst = (const int*)d_in[9];
    const int* gids = (const int*)d_in[10];

    const int N = in_sizes[0] / EMB;
    const int E = in_sizes[8];
    const int G = out_size / EMB;
    float* out = (float*)d_out;

    const int SMEM_BYTES = 3 * 4 * 16384;  // 192 KB, 3 stages
    cudaFuncSetAttribute(gemm_mma<1>, cudaFuncAttributeMaxDynamicSharedMemorySize, SMEM_BYTES);
    cudaFuncSetAttribute(gemm_mma<0>, cudaFuncAttributeMaxDynamicSharedMemorySize, SMEM_BYTES);

    float *h0, *h1;
    unsigned short *ahi, *alo, *h2hi, *h2lo, *wt1hi, *wt1lo, *wt2hi, *wt2lo;
    cudaGetSymbolAddress((void**)&h0, g_hbuf0);
    cudaGetSymbolAddress((void**)&h1, g_hbuf1);
    cudaGetSymbolAddress((void**)&ahi, g_ahi);
    cudaGetSymbolAddress((void**)&alo, g_alo);
    cudaGetSymbolAddress((void**)&h2hi, g_h2hi);
    cudaGetSymbolAddress((void**)&h2lo, g_h2lo);
    cudaGetSymbolAddress((void**)&wt1hi, g_wt1hi);
    cudaGetSymbolAddress((void**)&wt1lo, g_wt1lo);
    cudaGetSymbolAddress((void**)&wt2hi, g_wt2hi);
    cudaGetSymbolAddress((void**)&wt2lo, g_wt2lo);

    // weight prep + CSR build (once per launch)
    {
        long long t1 = (long long)NLAYERS * HID * KP1;
        prep_wt<<<(unsigned)((t1 + 255) / 256), 256>>>(W1, wt1hi, wt1lo, EMB, HID, KP1, t1);
        long long t2 = (long long)NLAYERS * EMB * KP2;
        prep_wt<<<(unsigned)((t2 + 255) / 256), 256>>>(W2, wt2hi, wt2lo, HID, EMB, KP2, t2);

        zero_deg<<<(N + 255) / 256, 256>>>(N);
        hist_dst<<<(E + 255) / 256, 256>>>(dst, E);
        scan_deg<<<1, 1024>>>(N);
        fill_csr<<<(E + 255) / 256, 256>>>(src, dst, E);
    }

    const long long nfeat = (long long)N * EMB;
    const long long n80 = (long long)N * 80;
    const int mtiles = (N + 127) / 128;

    const float* hin = node_feats;
    for (int l = 0; l < NLAYERS; l++) {
        float* hout = (l & 1) ? h1 : h0;

        gather_split<<<(unsigned)((n80 + 255) / 256), 256>>>(
            (const float4*)hin, eps, l, (uint2*)ahi, (uint2*)alo, n80, l > 0 ? 1 : 0);

        // gemm1: [N,320] x [600,320]^T -> h2 bf16 hi/lo [N,640] (relu, pads zeroed)
        gemm_mma<1><<<dim3(KP2 / 128, mtiles), 256, SMEM_BYTES>>>(
            ahi, alo, wt1hi + (size_t)l * HID * KP1, wt1lo + (size_t)l * HID * KP1,
            b1v + (size_t)l * HID, nullptr, h2hi, h2lo, N, HID, KP1, KP2);

        zero_stats<<<1, 512>>>();
        // gemm2: [N,640] x [300,640]^T -> hout fp32 [N,300] + BN stats
        gemm_mma<0><<<dim3((EMB + 127) / 128, mtiles), 256, SMEM_BYTES>>>(
            h2hi, h2lo, wt2hi + (size_t)l * EMB * KP2, wt2lo + (size_t)l * EMB * KP2,
            b2v + (size_t)l * EMB, hout, nullptr, nullptr, N, EMB, KP2, EMB);

        bn_finalize<<<1, 512>>>(gamma + (size_t)l * EMB, beta + (size_t)l * EMB, N);
        hin = hout;
    }

    zero_out_cnt<<<(G * EMB + 255) / 256, 256>>>(out, G);
    readout_cnt<<<(N + 255) / 256, 256>>>(gids, N);
    readout_accum<<<(unsigned)((nfeat / 4 + 255) / 256), 256>>>(hin, gids, out, nfeat / 4);
    readout_div<<<(G * EMB + 255) / 256, 256>>>(out, G);
}

// round 12
// speedup vs baseline: 1.1315x; 1.1315x over previous
#include <cuda_runtime.h>
#include <cuda_bf16.h>
#include <cstdint>

#define EMB 300
#define HID 600
#define KP1 320   // padded K for gemm1 (multiple of 64)
#define KP2 640   // padded K for gemm2
#define NLAYERS 5
#define NMAX 50176
#define EMAX 1000000
#define BN_EPS 1e-5f

// ---------------- scratch (static __device__ globals; no allocations) -------
__device__ __align__(128) float g_hbuf0[NMAX * EMB];
__device__ __align__(128) float g_hbuf1[NMAX * EMB];
__device__ __align__(128) unsigned short g_ahi[NMAX * KP1];
__device__ __align__(128) unsigned short g_alo[NMAX * KP1];
__device__ __align__(128) unsigned short g_h2hi[(size_t)NMAX * KP2];
__device__ __align__(128) unsigned short g_h2lo[(size_t)NMAX * KP2];
__device__ __align__(128) unsigned short g_wt1hi[NLAYERS * HID * KP1];
__device__ __align__(128) unsigned short g_wt1lo[NLAYERS * HID * KP1];
__device__ __align__(128) unsigned short g_wt2hi[NLAYERS * EMB * KP2];
__device__ __align__(128) unsigned short g_wt2lo[NLAYERS * EMB * KP2];
__device__ int g_deg[NMAX];
__device__ int g_rowptr[NMAX + 1];
__device__ int g_wofs[NMAX];
__device__ int g_csr[EMAX];
__device__ float g_sum[EMB], g_sumsq[EMB];
__device__ __align__(16) float g_scale[EMB];
__device__ __align__(16) float g_shift[EMB];
__device__ float g_cnt[4096];

// ---------------- PTX helpers -------------------------------------------------
__device__ __forceinline__ uint32_t smem_u32(const void* p) {
    uint32_t a;
    asm("{ .reg .u64 t; cvta.to.shared.u64 t, %1; cvt.u32.u64 %0, t; }" : "=r"(a) : "l"(p));
    return a;
}
__device__ __forceinline__ void cp16(uint32_t dsm, const void* gsrc, int sz) {
    asm volatile("cp.async.cg.shared.global [%0], [%1], 16, %2;"
                 :: "r"(dsm), "l"(gsrc), "r"(sz) : "memory");
}
#define CP_COMMIT() asm volatile("cp.async.commit_group;" ::: "memory")
#define CP_WAIT(n) asm volatile("cp.async.wait_group %0;" :: "n"(n) : "memory")

#define LDSM4(r, addr) \
    asm volatile("ldmatrix.sync.aligned.m8n8.x4.shared.b16 {%0,%1,%2,%3}, [%4];" \
                 : "=r"((r)[0]), "=r"((r)[1]), "=r"((r)[2]), "=r"((r)[3]) : "r"(addr))

#define MMA_BF16(d, a, b0, b1) \
    asm volatile("mma.sync.aligned.m16n8k16.row.col.f32.bf16.bf16.f32 " \
                 "{%0,%1,%2,%3}, {%4,%5,%6,%7}, {%8,%9}, {%0,%1,%2,%3};" \
                 : "+f"((d)[0]), "+f"((d)[1]), "+f"((d)[2]), "+f"((d)[3]) \
                 : "r"((a)[0]), "r"((a)[1]), "r"((a)[2]), "r"((a)[3]), "r"(b0), "r"(b1))

// ---------------- CSR build (once per launch) ---------------------------------
__global__ void zero_deg(int N) {
    int i = blockIdx.x * blockDim.x + threadIdx.x;
    if (i < N) g_deg[i] = 0;
}
__global__ void hist_dst(const int* __restrict__ dst, int E) {
    int e = blockIdx.x * blockDim.x + threadIdx.x;
    if (e < E) atomicAdd(&g_deg[__ldg(&dst[e])], 1);
}
__global__ void scan_deg(int N) {
    __shared__ int sm[1024];
    __shared__ int carry;
    int t = threadIdx.x;
    if (t == 0) carry = 0;
    __syncthreads();
    for (int base = 0; base < N; base += 1024) {
        int i = base + t;
        int v = (i < N) ? g_deg[i] : 0;
        sm[t] = v;
        __syncthreads();
#pragma unroll
        for (int off = 1; off < 1024; off <<= 1) {
            int x = (t >= off) ? sm[t - off] : 0;
            __syncthreads();
            sm[t] += x;
            __syncthreads();
        }
        if (i < N) {
            int ex = carry + sm[t] - v;
            g_rowptr[i] = ex;
            g_wofs[i] = ex;
        }
        __syncthreads();
        if (t == 1023) carry += sm[1023];
        __syncthreads();
    }
    if (t == 0) g_rowptr[N] = carry;
}
__global__ void fill_csr(const int* __restrict__ src, const int* __restrict__ dst, int E) {
    int e = blockIdx.x * blockDim.x + threadIdx.x;
    if (e >= E) return;
    int d = __ldg(&dst[e]);
    int p = atomicAdd(&g_wofs[d], 1);
    g_csr[p] = __ldg(&src[e]);
}

// ---------------- fused (BN+relu of prev layer) + gather + (1+eps) + split ----
__global__ void gather_split(const float4* __restrict__ h, const float* __restrict__ eps,
                             int l, uint2* __restrict__ oh, uint2* __restrict__ ol,
                             long long n80, int apply_bn) {
    long long i = blockIdx.x * 256LL + threadIdx.x;
    if (i >= n80) return;
    int n = (int)(i / 80);
    int c = (int)(i % 80);
    if (c >= 75) {
        if (!apply_bn) {  // pads written once (layer 0); stay zero afterwards
            uint2 z = make_uint2(0u, 0u);
            oh[i] = z;
            ol[i] = z;
        }
        return;
    }
    float4 sc, sh;
    if (apply_bn) {
        sc = reinterpret_cast<const float4*>(g_scale)[c];
        sh = reinterpret_cast<const float4*>(g_shift)[c];
    }
    float e = 1.0f + __ldg(&eps[l]);
    float4 v = h[(size_t)n * 75 + c];
    if (apply_bn) {
        v.x = fmaxf(fmaf(v.x, sc.x, sh.x), 0.f);
        v.y = fmaxf(fmaf(v.y, sc.y, sh.y), 0.f);
        v.z = fmaxf(fmaf(v.z, sc.z, sh.z), 0.f);
        v.w = fmaxf(fmaf(v.w, sc.w, sh.w), 0.f);
    }
    v.x *= e; v.y *= e; v.z *= e; v.w *= e;
    int p0 = __ldg(&g_rowptr[n]);
    int p1 = __ldg(&g_rowptr[n + 1]);
    for (int p = p0; p < p1; p++) {
        int s = __ldg(&g_csr[p]);
        float4 u = __ldg(&h[(size_t)s * 75 + c]);
        if (apply_bn) {
            u.x = fmaxf(fmaf(u.x, sc.x, sh.x), 0.f);
            u.y = fmaxf(fmaf(u.y, sc.y, sh.y), 0.f);
            u.z = fmaxf(fmaf(u.z, sc.z, sh.z), 0.f);
            u.w = fmaxf(fmaf(u.w, sc.w, sh.w), 0.f);
        }
        v.x += u.x; v.y += u.y; v.z += u.z; v.w += u.w;
    }
    __nv_bfloat16 h0 = __float2bfloat16(v.x), h1 = __float2bfloat16(v.y);
    __nv_bfloat16 h2 = __float2bfloat16(v.z), h3 = __float2bfloat16(v.w);
    __nv_bfloat16 l0 = __float2bfloat16(v.x - __bfloat162float(h0));
    __nv_bfloat16 l1 = __float2bfloat16(v.y - __bfloat162float(h1));
    __nv_bfloat16 l2 = __float2bfloat16(v.z - __bfloat162float(h2));
    __nv_bfloat16 l3 = __float2bfloat16(v.w - __bfloat162float(h3));
    __nv_bfloat162 ph0 = __halves2bfloat162(h0, h1), ph1 = __halves2bfloat162(h2, h3);
    __nv_bfloat162 pl0 = __halves2bfloat162(l0, l1), pl1 = __halves2bfloat162(l2, l3);
    oh[i] = make_uint2(*reinterpret_cast<uint32_t*>(&ph0), *reinterpret_cast<uint32_t*>(&ph1));
    ol[i] = make_uint2(*reinterpret_cast<uint32_t*>(&pl0), *reinterpret_cast<uint32_t*>(&pl1));
}

// ---------------- prep: split weights into transposed bf16 hi/lo -------------
__global__ void prep_wt(const float* __restrict__ W, unsigned short* __restrict__ wh,
                        unsigned short* __restrict__ wl, int K, int Nd, int kpad, long long total) {
    long long i = blockIdx.x * 256LL + threadIdx.x;
    if (i >= total) return;
    int k = (int)(i % kpad);
    long long r = i / kpad;
    int n = (int)(r % Nd);
    int l = (int)(r / Nd);
    float v = 0.f;
    if (k < K) v = W[((size_t)l * K + k) * Nd + n];
    __nv_bfloat16 hi = __float2bfloat16(v);
    __nv_bfloat16 lo = __float2bfloat16(v - __bfloat162float(hi));
    wh[i] = *reinterpret_cast<unsigned short*>(&hi);
    wl[i] = *reinterpret_cast<unsigned short*>(&lo);
}

__global__ void zero_stats() {
    int t = threadIdx.x;
    if (t < EMB) { g_sum[t] = 0.f; g_sumsq[t] = 0.f; }
}
__global__ void zero_out_cnt(float* __restrict__ out, int G) {
    int i = blockIdx.x * blockDim.x + threadIdx.x;
    if (i < G * EMB) out[i] = 0.f;
    if (i < G) g_cnt[i] = 0.f;
}

// ---------------- HMMA bf16 GEMM (3-term split) --------------------------------
// Block tile 128(M) x 64(N), K-chunk 64, 2-stage cp.async, 2 CTAs/SM.
// 8 warps: 4 along M (32 rows), 2 along N (32 cols).
// OUT_BF16=1: o = relu(d+bias) -> Chi/Clo bf16, pads zeroed.
// OUT_BF16=0: o = d+bias -> Cf fp32, AND per-column sum/sumsq atomics (BN stats).
template <int OUT_BF16>
__global__ __launch_bounds__(256, 2) void gemm_mma(
    const unsigned short* __restrict__ Ahi, const unsigned short* __restrict__ Alo,
    const unsigned short* __restrict__ Bhi, const unsigned short* __restrict__ Blo,
    const float* __restrict__ bias, float* __restrict__ Cf,
    unsigned short* __restrict__ Chi, unsigned short* __restrict__ Clo,
    int M, int Nd, int kpad, int cpad) {
    extern __shared__ char smem[];
    const uint32_t sb = smem_u32(smem);
    const int tid = threadIdx.x;
    const int wid = tid >> 5;
    const int lid = tid & 31;
    const int wm = wid & 3;   // 4 warps along M (32 rows each)
    const int wn = wid >> 2;  // 2 warps along N (32 cols each)
    const int m0 = blockIdx.y * 128;
    const int n0 = blockIdx.x * 64;
    const int g = lid >> 2;
    const int tig = lid & 3;

    // smem per stage: Ah@0 (16K), Al@16K, Bh@32K (8K), Bl@40K; stage stride 48K.
    const int NC = kpad >> 6;
    const int lrow = tid >> 1;         // A loader: row 0..127
    const int lcb = (tid & 1) * 4;     // A loader: chunk base
    const int blrow = tid >> 2;        // B loader: row 0..63
    const int bcb = (tid & 3) * 2;     // B loader: chunk base

    auto issue_load = [&](int c) {
        const int k0 = c << 6;
        const uint32_t bbase = sb + (c & 1) * 49152;
        {
            const int gr = m0 + lrow;
            const int ok = (gr < M) ? 16 : 0;
            const size_t rowoff = (size_t)(ok ? gr : 0) * kpad + k0 + lcb * 8;
            const uint32_t mb = bbase + lrow * 128;
            const int rsw = lrow & 7;
#pragma unroll
            for (int i = 0; i < 4; i++) {
                int chunk = lcb + i;
                uint32_t so = ((chunk ^ rsw) << 4);
                cp16(mb + so, Ahi + rowoff + i * 8, ok);
                cp16(mb + 16384 + so, Alo + rowoff + i * 8, ok);
            }
        }
        {
            const int gr = n0 + blrow;
            const int ok = (gr < Nd) ? 16 : 0;
            const size_t rowoff = (size_t)(ok ? gr : 0) * kpad + k0 + bcb * 8;
            const uint32_t mb = bbase + 32768 + blrow * 128;
            const int rsw = blrow & 7;
#pragma unroll
            for (int i = 0; i < 2; i++) {
                int chunk = bcb + i;
                uint32_t so = ((chunk ^ rsw) << 4);
                cp16(mb + so, Bhi + rowoff + i * 8, ok);
                cp16(mb + 8192 + so, Blo + rowoff + i * 8, ok);
            }
        }
        CP_COMMIT();
    };

    float acc[2][4][4];
#pragma unroll
    for (int a = 0; a < 2; a++)
#pragma unroll
        for (int b = 0; b < 4; b++)
#pragma unroll
            for (int c = 0; c < 4; c++) acc[a][b][c] = 0.f;

    const int arow = (lid & 15);
    const int achk = (lid >> 4);
    const int brow = (lid & 7) + ((lid & 16) ? 8 : 0);
    const int bchk = (lid >> 3) & 1;

    issue_load(0);

    for (int c = 0; c < NC; c++) {
        if (c + 1 < NC) { issue_load(c + 1); CP_WAIT(1); }
        else CP_WAIT(0);
        __syncthreads();

        const uint32_t bbase = sb + (c & 1) * 49152;
        const uint32_t sAh = bbase, sAl = bbase + 16384;
        const uint32_t sBh = bbase + 32768, sBl = bbase + 40960;

#pragma unroll
        for (int ks = 0; ks < 4; ks++) {
            const int kb8 = ks * 2;
            uint32_t aH[2][4], aL[2][4], bH[2][4], bL[2][4];
#pragma unroll
            for (int mi = 0; mi < 2; mi++) {
                int row = wm * 32 + mi * 16 + arow;
                int chunk = kb8 + achk;
                uint32_t off = row * 128 + ((chunk ^ (row & 7)) << 4);
                LDSM4(aH[mi], sAh + off);
                LDSM4(aL[mi], sAl + off);
            }
#pragma unroll
            for (int nj = 0; nj < 2; nj++) {
                int row = wn * 32 + nj * 16 + brow;
                int chunk = kb8 + bchk;
                uint32_t off = row * 128 + ((chunk ^ (row & 7)) << 4);
                LDSM4(bH[nj], sBh + off);
                LDSM4(bL[nj], sBl + off);
            }
#pragma unroll
            for (int mi = 0; mi < 2; mi++)
#pragma unroll
                for (int nj = 0; nj < 2; nj++)
#pragma unroll
                    for (int h = 0; h < 2; h++) {
                        float* d = acc[mi][nj * 2 + h];
                        MMA_BF16(d, aH[mi], bH[nj][h * 2], bH[nj][h * 2 + 1]);
                        MMA_BF16(d, aL[mi], bH[nj][h * 2], bH[nj][h * 2 + 1]);
                        MMA_BF16(d, aH[mi], bL[nj][h * 2], bL[nj][h * 2 + 1]);
                    }
        }
        __syncthreads();
    }

    // epilogue (+ BN stats accumulation when OUT_BF16==0)
    float sacc[4][2], s2acc[4][2];
#pragma unroll
    for (int nj = 0; nj < 4; nj++) { sacc[nj][0] = sacc[nj][1] = 0.f; s2acc[nj][0] = s2acc[nj][1] = 0.f; }

#pragma unroll
    for (int mi = 0; mi < 2; mi++) {
#pragma unroll
        for (int nj = 0; nj < 4; nj++) {
            const float* d = acc[mi][nj];
            int c = n0 + wn * 32 + nj * 8 + 2 * tig;
            float bs0 = 0.f, bs1 = 0.f;
            if (c < Nd) bs0 = __ldg(&bias[c]);
            if (c + 1 < Nd) bs1 = __ldg(&bias[c + 1]);
#pragma unroll
            for (int half = 0; half < 2; half++) {
                int r = m0 + wm * 32 + mi * 16 + g + half * 8;
                if (r >= M) continue;
                float o0 = (c < Nd) ? d[half * 2] + bs0 : 0.f;
                float o1 = (c + 1 < Nd) ? d[half * 2 + 1] + bs1 : 0.f;
                if (OUT_BF16) {
                    o0 = fmaxf(o0, 0.f);
                    o1 = fmaxf(o1, 0.f);
                    __nv_bfloat16 h0 = __float2bfloat16(o0), h1 = __float2bfloat16(o1);
                    __nv_bfloat16 l0 = __float2bfloat16(o0 - __bfloat162float(h0));
                    __nv_bfloat16 l1 = __float2bfloat16(o1 - __bfloat162float(h1));
                    __nv_bfloat162 ph = __halves2bfloat162(h0, h1);
                    __nv_bfloat162 pl = __halves2bfloat162(l0, l1);
                    *reinterpret_cast<uint32_t*>(Chi + (size_t)r * cpad + c) =
                        *reinterpret_cast<uint32_t*>(&ph);
                    *reinterpret_cast<uint32_t*>(Clo + (size_t)r * cpad + c) =
                        *reinterpret_cast<uint32_t*>(&pl);
                } else {
                    if (c < Nd) {
                        float2 v = make_float2(o0, o1);
                        *reinterpret_cast<float2*>(Cf + (size_t)r * cpad + c) = v;
                    }
                    sacc[nj][0] += o0;
                    s2acc[nj][0] += o0 * o0;
                    sacc[nj][1] += o1;
                    s2acc[nj][1] += o1 * o1;
                }
            }
        }
    }

    if (!OUT_BF16) {
        __syncthreads();
        float* st = reinterpret_cast<float*>(smem);
        if (tid < 128) st[tid] = 0.f;
        __syncthreads();
#pragma unroll
        for (int nj = 0; nj < 4; nj++) {
#pragma unroll
            for (int cp = 0; cp < 2; cp++) {
                float s = sacc[nj][cp], s2 = s2acc[nj][cp];
                s += __shfl_xor_sync(0xFFFFFFFFu, s, 4);
                s2 += __shfl_xor_sync(0xFFFFFFFFu, s2, 4);
                s += __shfl_xor_sync(0xFFFFFFFFu, s, 8);
                s2 += __shfl_xor_sync(0xFFFFFFFFu, s2, 8);
                s += __shfl_xor_sync(0xFFFFFFFFu, s, 16);
                s2 += __shfl_xor_sync(0xFFFFFFFFu, s2, 16);
                if (g == 0) {
                    int cl = wn * 32 + nj * 8 + 2 * tig + cp;
                    atomicAdd(&st[cl], s);
                    atomicAdd(&st[64 + cl], s2);
                }
            }
        }
        __syncthreads();
        if (tid < 64) {
            int c = n0 + tid;
            if (c < Nd) {
                atomicAdd(&g_sum[c], st[tid]);
                atomicAdd(&g_sumsq[c], st[64 + tid]);
            }
        }
    }
}

// ---------------- BN finalize: scale/shift per channel -------------------------
__global__ void bn_finalize(const float* __restrict__ gamma, const float* __restrict__ beta,
                            int N) {
    int c = threadIdx.x;
    if (c >= EMB) return;
    float invN = 1.0f / (float)N;
    float mu = g_sum[c] * invN;
    float var = g_sumsq[c] * invN - mu * mu;
    float istd = rsqrtf(var + BN_EPS);
    float sc = istd * __ldg(&gamma[c]);
    g_scale[c] = sc;
    g_shift[c] = __ldg(&beta[c]) - mu * sc;
}

// ---------------- readout (applies last layer's BN, no relu) -------------------
__global__ void readout_cnt(const int* __restrict__ gids, int N) {
    int n = blockIdx.x * blockDim.x + threadIdx.x;
    if (n < N) atomicAdd(&g_cnt[__ldg(&gids[n])], 1.0f);
}
__global__ void readout_accum(const float* __restrict__ h, const int* __restrict__ gids,
                              float* __restrict__ out, long long total) {
    long long idx = blockIdx.x * 256LL + threadIdx.x;
    if (idx >= total) return;
    int n = (int)(idx / 75);
    int c = (int)(idx % 75);
    int g = __ldg(&gids[n]);
    float4 sc = reinterpret_cast<const float4*>(g_scale)[c];
    float4 sh = reinterpret_cast<const float4*>(g_shift)[c];
    float4 v = reinterpret_cast<const float4*>(h + (size_t)n * EMB)[c];
    v.x = fmaf(v.x, sc.x, sh.x);
    v.y = fmaf(v.y, sc.y, sh.y);
    v.z = fmaf(v.z, sc.z, sh.z);
    v.w = fmaf(v.w, sc.w, sh.w);
    atomicAdd(reinterpret_cast<float4*>(out + (size_t)g * EMB) + c, v);
}
__global__ void readout_div(float* __restrict__ out, int G) {
    int i = blockIdx.x * blockDim.x + threadIdx.x;
    if (i < G * EMB) out[i] /= fmaxf(g_cnt[i / EMB], 1.0f);
}

// ---------------- launch ------------------------------------------------------
extern "C" void kernel_launch(void* const* d_in, const int* in_sizes, int n_in,
                              void* d_out, int out_size) {
    (void)n_in;
    const float* node_feats = (const float*)d_in[0];
    const float* W1 = (const float*)d_in[1];
    const float* b1v = (const float*)d_in[2];
    const float* W2 = (const float*)d_in[3];
    const float* b2v = (const float*)d_in[4];
    const float* eps = (const float*)d_in[5];
    const float* gamma = (const float*)d_in[6];
    const float* beta = (const float*)d_in[7];
    const int* src = (const int*)d_in[8];
    const int* dst = (const int*)d_in[9];
    const int* gids = (const int*)d_in[10];

    const int N = in_sizes[0] / EMB;
    const int E = in_sizes[8];
    const int G = out_size / EMB;
    float* out = (float*)d_out;

    const int SMEM_BYTES = 2 * 49152;  // 96 KB -> 2 CTAs/SM
    cudaFuncSetAttribute(gemm_mma<1>, cudaFuncAttributeMaxDynamicSharedMemorySize, SMEM_BYTES);
    cudaFuncSetAttribute(gemm_mma<0>, cudaFuncAttributeMaxDynamicSharedMemorySize, SMEM_BYTES);

    float *h0, *h1;
    unsigned short *ahi, *alo, *h2hi, *h2lo, *wt1hi, *wt1lo, *wt2hi, *wt2lo;
    cudaGetSymbolAddress((void**)&h0, g_hbuf0);
    cudaGetSymbolAddress((void**)&h1, g_hbuf1);
    cudaGetSymbolAddress((void**)&ahi, g_ahi);
    cudaGetSymbolAddress((void**)&alo, g_alo);
    cudaGetSymbolAddress((void**)&h2hi, g_h2hi);
    cudaGetSymbolAddress((void**)&h2lo, g_h2lo);
    cudaGetSymbolAddress((void**)&wt1hi, g_wt1hi);
    cudaGetSymbolAddress((void**)&wt1lo, g_wt1lo);
    cudaGetSymbolAddress((void**)&wt2hi, g_wt2hi);
    cudaGetSymbolAddress((void**)&wt2lo, g_wt2lo);

    // weight prep + CSR build (once per launch)
    {
        long long t1 = (long long)NLAYERS * HID * KP1;
        prep_wt<<<(unsigned)((t1 + 255) / 256), 256>>>(W1, wt1hi, wt1lo, EMB, HID, KP1, t1);
        long long t2 = (long long)NLAYERS * EMB * KP2;
        prep_wt<<<(unsigned)((t2 + 255) / 256), 256>>>(W2, wt2hi, wt2lo, HID, EMB, KP2, t2);

        zero_deg<<<(N + 255) / 256, 256>>>(N);
        hist_dst<<<(E + 255) / 256, 256>>>(dst, E);
        scan_deg<<<1, 1024>>>(N);
        fill_csr<<<(E + 255) / 256, 256>>>(src, dst, E);
    }

    const long long nfeat = (long long)N * EMB;
    const long long n80 = (long long)N * 80;
    const int mtiles = (N + 127) / 128;

    const float* hin = node_feats;
    for (int l = 0; l < NLAYERS; l++) {
        float* hout = (l & 1) ? h1 : h0;

        gather_split<<<(unsigned)((n80 + 255) / 256), 256>>>(
            (const float4*)hin, eps, l, (uint2*)ahi, (uint2*)alo, n80, l > 0 ? 1 : 0);

        // gemm1: [N,320] x [600,320]^T -> h2 bf16 hi/lo [N,640] (relu, pads zeroed)
        gemm_mma<1><<<dim3(KP2 / 64, mtiles), 256, SMEM_BYTES>>>(
            ahi, alo, wt1hi + (size_t)l * HID * KP1, wt1lo + (size_t)l * HID * KP1,
            b1v + (size_t)l * HID, nullptr, h2hi, h2lo, N, HID, KP1, KP2);

        zero_stats<<<1, 512>>>();
        // gemm2: [N,640] x [300,640]^T -> hout fp32 [N,300] + BN stats
        gemm_mma<0><<<dim3((EMB + 63) / 64, mtiles), 256, SMEM_BYTES>>>(
            h2hi, h2lo, wt2hi + (size_t)l * EMB * KP2, wt2lo + (size_t)l * EMB * KP2,
            b2v + (size_t)l * EMB, hout, nullptr, nullptr, N, EMB, KP2, EMB);

        bn_finalize<<<1, 512>>>(gamma + (size_t)l * EMB, beta + (size_t)l * EMB, N);
        hin = hout;
    }

    zero_out_cnt<<<(G * EMB + 255) / 256, 256>>>(out, G);
    readout_cnt<<<(N + 255) / 256, 256>>>(gids, N);
    readout_accum<<<(unsigned)((nfeat / 4 + 255) / 256), 256>>>(hin, gids, out, nfeat / 4);
    readout_div<<<(G * EMB + 255) / 256, 256>>>(out, G);
}